// round 2
// baseline (speedup 1.0000x reference)
#include <cuda_runtime.h>

#define H 64
#define IN_DIM 16
#define NMAX 50048
#define EMAX 800000

// scratch (allocation-free rule: __device__ globals)
__device__ float g_dinv[NMAX];
__device__ float g_norm[EMAX];
__device__ float g_h[NMAX * H];
__device__ float g_t[NMAX * H];
__device__ float g_agg[NMAX * H];

// ---------------- degree / norm precompute ----------------

__global__ void fill_ones(int N) {
    int i = blockIdx.x * blockDim.x + threadIdx.x;
    if (i < N) g_dinv[i] = 1.0f;  // self-loop contributes 1 to every degree
}

__global__ void deg_kernel(const int* __restrict__ col, int E) {
    int e = blockIdx.x * blockDim.x + threadIdx.x;
    if (e < E) atomicAdd(&g_dinv[col[e]], 1.0f);
}

__global__ void rsqrt_kernel(int N) {
    int i = blockIdx.x * blockDim.x + threadIdx.x;
    if (i < N) g_dinv[i] = rsqrtf(g_dinv[i]);  // deg >= 1 always (self-loop)
}

__global__ void norm_kernel(const int* __restrict__ ei, int E) {
    int e = blockIdx.x * blockDim.x + threadIdx.x;
    if (e < E) g_norm[e] = g_dinv[ei[e]] * g_dinv[ei[E + e]];
}

// ---------------- input GEMM: h = relu(x @ W_in + b_in) ----------------
// block = 256 threads (64 j-cols x 4 node-subsets), 32 nodes per block

__global__ void in_gemm(const float* __restrict__ x, const float* __restrict__ Win,
                        const float* __restrict__ bin, int N) {
    __shared__ float sW[IN_DIM * H];   // 4 KB
    __shared__ float sx[32][IN_DIM];   // 2 KB
    int tid = threadIdx.x;
    for (int i = tid; i < IN_DIM * H; i += 256) sW[i] = Win[i];
    int base = blockIdx.x * 32;
    for (int i = tid; i < 32 * IN_DIM; i += 256) {
        int n = i / IN_DIM, k = i % IN_DIM;
        int node = base + n;
        sx[n][k] = (node < N) ? x[node * IN_DIM + k] : 0.0f;
    }
    __syncthreads();
    int j = tid & 63, sub = tid >> 6;
    float bj = bin[j];
    for (int n = sub; n < 32; n += 4) {
        int node = base + n;
        if (node >= N) break;
        float acc = bj;
#pragma unroll
        for (int k = 0; k < IN_DIM; k++) acc += sx[n][k] * sW[k * H + j];
        g_h[node * H + j] = fmaxf(acc, 0.0f);
    }
}

// ---------------- per-layer transform: t = h @ W; agg = b + t * dinv^2 ----------------
// block = 256 threads, 64 nodes per block. W column held in registers (64 regs),
// h tile staged in shared (broadcast reads, conflict-free).

__global__ void conv_gemm(const float* __restrict__ W, const float* __restrict__ b, int N) {
    __shared__ float sh[64][H];  // 16 KB
    int tid = threadIdx.x;
    int j = tid & 63, sub = tid >> 6;
    int base = blockIdx.x * 64;
    int nn = N - base;
    if (nn > 64) nn = 64;
    if (nn <= 0) return;

    float w[H];
#pragma unroll
    for (int k = 0; k < H; k++) w[k] = W[k * H + j];  // coalesced across j

    const float4* hsrc = (const float4*)&g_h[base * H];
    float4* sdst = (float4*)sh;
    int nvec = nn * (H / 4);
    for (int i = tid; i < nvec; i += 256) sdst[i] = hsrc[i];
    __syncthreads();

    float bj = b[j];
    for (int n = sub; n < nn; n += 4) {
        float acc = 0.0f;
#pragma unroll
        for (int k = 0; k < H; k++) acc += sh[n][k] * w[k];
        int node = base + n;
        g_t[node * H + j] = acc;
        float d = g_dinv[node];
        g_agg[node * H + j] = bj + acc * d * d;  // bias + self-loop message
    }
}

// ---------------- edge scatter: agg[col] += t[row] * norm  ----------------
// 16 lanes per edge, one float4 per lane, vector reduction to L2.

__global__ void scatter_kernel(const int* __restrict__ ei, int E) {
    int gt = blockIdx.x * blockDim.x + threadIdx.x;
    int e = gt >> 4;
    if (e >= E) return;
    int r = gt & 15;
    int row = ei[e];
    int col = ei[E + e];
    float nrm = g_norm[e];
    float4 v = *(const float4*)&g_t[row * H + r * 4];
    float4* dst = (float4*)&g_agg[col * H + r * 4];
    asm volatile("red.global.add.v4.f32 [%0], {%1,%2,%3,%4};"
                 :: "l"(dst), "f"(v.x * nrm), "f"(v.y * nrm), "f"(v.z * nrm), "f"(v.w * nrm)
                 : "memory");
}

// ---------------- layernorm + relu + residual (+ fused output head on last layer) ----------------
// one warp per node, 2 elements per lane

__global__ void ln_kernel(const float* __restrict__ gamma, const float* __restrict__ beta,
                          const float* __restrict__ Wout, const float* __restrict__ bout,
                          float* __restrict__ out, int N, int last) {
    int node = (blockIdx.x * blockDim.x + threadIdx.x) >> 5;
    int lane = threadIdx.x & 31;
    if (node >= N) return;
    const float* a = &g_agg[node * H];
    float a0 = a[lane], a1 = a[lane + 32];
    float s = a0 + a1;
#pragma unroll
    for (int o = 16; o; o >>= 1) s += __shfl_xor_sync(0xFFFFFFFFu, s, o);
    float mu = s * (1.0f / 64.0f);
    float d0 = a0 - mu, d1 = a1 - mu;
    float v = d0 * d0 + d1 * d1;
#pragma unroll
    for (int o = 16; o; o >>= 1) v += __shfl_xor_sync(0xFFFFFFFFu, v, o);
    float inv = rsqrtf(v * (1.0f / 64.0f) + 1e-5f);
    float r0 = fmaxf(d0 * inv * gamma[lane] + beta[lane], 0.0f) + g_h[node * H + lane];
    float r1 = fmaxf(d1 * inv * gamma[lane + 32] + beta[lane + 32], 0.0f) + g_h[node * H + lane + 32];
    g_h[node * H + lane] = r0;
    g_h[node * H + lane + 32] = r1;
    if (last) {
        float o_ = r0 * Wout[lane] + r1 * Wout[lane + 32];
#pragma unroll
        for (int o = 16; o; o >>= 1) o_ += __shfl_xor_sync(0xFFFFFFFFu, o_, o);
        if (lane == 0) out[node] = o_ + bout[0];
    }
}

// ---------------- launch ----------------

extern "C" void kernel_launch(void* const* d_in, const int* in_sizes, int n_in,
                              void* d_out, int out_size) {
    const float* x      = (const float*)d_in[0];
    const int*   ei     = (const int*)d_in[1];
    const float* W_in   = (const float*)d_in[2];
    const float* b_in   = (const float*)d_in[3];
    const float* W_conv = (const float*)d_in[4];
    const float* b_conv = (const float*)d_in[5];
    const float* gamma  = (const float*)d_in[6];
    const float* beta   = (const float*)d_in[7];
    const float* W_out  = (const float*)d_in[8];
    const float* b_out  = (const float*)d_in[9];
    float* out = (float*)d_out;

    int N = in_sizes[0] / IN_DIM;
    int E = in_sizes[1] / 2;

    fill_ones<<<(N + 255) / 256, 256>>>(N);
    deg_kernel<<<(E + 255) / 256, 256>>>(ei + E, E);
    rsqrt_kernel<<<(N + 255) / 256, 256>>>(N);
    norm_kernel<<<(E + 255) / 256, 256>>>(ei, E);

    in_gemm<<<(N + 31) / 32, 256>>>(x, W_in, b_in, N);

    long long scatter_threads = (long long)E * 16;
    int scatter_blocks = (int)((scatter_threads + 255) / 256);

    for (int l = 0; l < 3; l++) {
        conv_gemm<<<(N + 63) / 64, 256>>>(W_conv + l * H * H, b_conv + l * H, N);
        scatter_kernel<<<scatter_blocks, 256>>>(ei, E);
        ln_kernel<<<(N * 32 + 255) / 256, 256>>>(gamma + l * H, beta + l * H,
                                                 W_out, b_out, out, N, l == 2);
    }
}

// round 4
// speedup vs baseline: 1.3902x; 1.3902x over previous
#include <cuda_runtime.h>

#define H 64
#define IN_DIM 16
#define NMAX 50048
#define EMAX 800000

// scratch (allocation-free rule: __device__ globals)
__device__ float g_dinv[NMAX];
__device__ float g_h[NMAX * H];
__device__ float g_t[NMAX * H];
__device__ int   g_cnt[NMAX];       // in-degree counts (excl self-loop)
__device__ int   g_rowptr[NMAX + 1];
__device__ int   g_wr[NMAX];        // write cursors for CSR fill
__device__ int   g_src[EMAX];       // CSR: source node per slot
__device__ float g_en[EMAX];        // CSR: edge norm per slot
__device__ int   g_bsum[64];        // scan block sums

// ---------------- CSR build ----------------

__global__ void zero_cnt(int N) {
    int i = blockIdx.x * blockDim.x + threadIdx.x;
    if (i < N) g_cnt[i] = 0;
}

__global__ void count_kernel(const int* __restrict__ col, int E) {
    int e = blockIdx.x * blockDim.x + threadIdx.x;
    if (e < E) atomicAdd(&g_cnt[col[e]], 1);
}

// block-level exclusive scan (1024 elems/block)
__global__ void scanA(int N) {
    __shared__ int s[1024];
    int tid = threadIdx.x;
    int i = blockIdx.x * 1024 + tid;
    int v = (i < N) ? g_cnt[i] : 0;
    s[tid] = v;
    __syncthreads();
    for (int o = 1; o < 1024; o <<= 1) {
        int t = (tid >= o) ? s[tid - o] : 0;
        __syncthreads();
        s[tid] += t;
        __syncthreads();
    }
    if (i < N) g_rowptr[i] = s[tid] - v;  // exclusive within block
    if (tid == 1023) g_bsum[blockIdx.x] = s[1023];
}

__global__ void scanB(int nblk) {
    if (threadIdx.x == 0) {
        int acc = 0;
        for (int i = 0; i < nblk; i++) { int t = g_bsum[i]; g_bsum[i] = acc; acc += t; }
    }
}

__global__ void scanC(int N, int E) {
    int i = blockIdx.x * blockDim.x + threadIdx.x;
    if (i < N) {
        int rp = g_rowptr[i] + g_bsum[i >> 10];
        g_rowptr[i] = rp;
        g_wr[i] = rp;
        g_dinv[i] = rsqrtf((float)g_cnt[i] + 1.0f);  // +1 self-loop
    }
    if (i == 0) g_rowptr[N] = E;
}

__global__ void build_kernel(const int* __restrict__ ei, int E) {
    int e = blockIdx.x * blockDim.x + threadIdx.x;
    if (e >= E) return;
    int r = ei[e], c = ei[E + e];
    int slot = atomicAdd(&g_wr[c], 1);
    g_src[slot] = r;
    g_en[slot] = g_dinv[r] * g_dinv[c];
}

// ---------------- input GEMM: h = relu(x @ W_in + b_in) ----------------

__global__ void in_gemm(const float* __restrict__ x, const float* __restrict__ Win,
                        const float* __restrict__ bin, int N) {
    __shared__ float sW[IN_DIM * H];
    __shared__ float sx[32][IN_DIM];
    int tid = threadIdx.x;
    for (int i = tid; i < IN_DIM * H; i += 256) sW[i] = Win[i];
    int base = blockIdx.x * 32;
    for (int i = tid; i < 32 * IN_DIM; i += 256) {
        int n = i / IN_DIM, k = i % IN_DIM;
        int node = base + n;
        sx[n][k] = (node < N) ? x[node * IN_DIM + k] : 0.0f;
    }
    __syncthreads();
    int j = tid & 63, sub = tid >> 6;
    float bj = bin[j];
    for (int n = sub; n < 32; n += 4) {
        int node = base + n;
        if (node >= N) break;
        float acc = bj;
#pragma unroll
        for (int k = 0; k < IN_DIM; k++) acc += sx[n][k] * sW[k * H + j];
        g_h[node * H + j] = fmaxf(acc, 0.0f);
    }
}

// ---------------- per-layer transform: t = h @ W ----------------

__global__ void conv_gemm(const float* __restrict__ W, int N) {
    __shared__ float sh[64][H];  // 16 KB
    int tid = threadIdx.x;
    int j = tid & 63, sub = tid >> 6;
    int base = blockIdx.x * 64;
    int nn = N - base;
    if (nn > 64) nn = 64;
    if (nn <= 0) return;

    float w[H];
#pragma unroll
    for (int k = 0; k < H; k++) w[k] = W[k * H + j];

    const float4* hsrc = (const float4*)&g_h[base * H];
    float4* sdst = (float4*)sh;
    int nvec = nn * (H / 4);
    for (int i = tid; i < nvec; i += 256) sdst[i] = hsrc[i];
    __syncthreads();

    for (int n = sub; n < nn; n += 4) {
        float acc = 0.0f;
#pragma unroll
        for (int k = 0; k < H; k++) acc += sh[n][k] * w[k];
        g_t[(base + n) * H + j] = acc;
    }
}

// ---------------- fused gather + bias + self-loop + LN + ReLU + residual (+ head) ----------------
// one warp per node; lane owns features (2*lane, 2*lane+1) as float2

__global__ void gather_ln(const float* __restrict__ b,
                          const float* __restrict__ gamma, const float* __restrict__ beta,
                          const float* __restrict__ Wout, const float* __restrict__ bout,
                          float* __restrict__ out, int N, int last) {
    int node = (blockIdx.x * blockDim.x + threadIdx.x) >> 5;
    int lane = threadIdx.x & 31;
    if (node >= N) return;

    const float2* t2 = (const float2*)g_t;
    float d = g_dinv[node];
    float2 b2 = ((const float2*)b)[lane];
    float2 tn = t2[node * 32 + lane];
    float accx = b2.x + tn.x * d * d;   // bias + self-loop message
    float accy = b2.y + tn.y * d * d;

    int s = g_rowptr[node], e = g_rowptr[node + 1];
    int j = s;
    for (; j + 4 <= e; j += 4) {
        int r0 = g_src[j], r1 = g_src[j + 1], r2 = g_src[j + 2], r3 = g_src[j + 3];
        float n0 = g_en[j], n1 = g_en[j + 1], n2 = g_en[j + 2], n3 = g_en[j + 3];
        float2 v0 = t2[r0 * 32 + lane];
        float2 v1 = t2[r1 * 32 + lane];
        float2 v2 = t2[r2 * 32 + lane];
        float2 v3 = t2[r3 * 32 + lane];
        accx += v0.x * n0 + v1.x * n1 + v2.x * n2 + v3.x * n3;
        accy += v0.y * n0 + v1.y * n1 + v2.y * n2 + v3.y * n3;
    }
    for (; j < e; ++j) {
        int r = g_src[j];
        float nm = g_en[j];
        float2 v = t2[r * 32 + lane];
        accx += v.x * nm;
        accy += v.y * nm;
    }

    // layernorm over 64 features
    float ssum = accx + accy;
#pragma unroll
    for (int o = 16; o; o >>= 1) ssum += __shfl_xor_sync(0xFFFFFFFFu, ssum, o);
    float mu = ssum * (1.0f / 64.0f);
    float dx = accx - mu, dy = accy - mu;
    float var = dx * dx + dy * dy;
#pragma unroll
    for (int o = 16; o; o >>= 1) var += __shfl_xor_sync(0xFFFFFFFFu, var, o);
    float inv = rsqrtf(var * (1.0f / 64.0f) + 1e-5f);

    float2 g2 = ((const float2*)gamma)[lane];
    float2 be2 = ((const float2*)beta)[lane];
    float2* hp = (float2*)&g_h[node * H];
    float2 hres = hp[lane];
    float r0 = fmaxf(dx * inv * g2.x + be2.x, 0.0f) + hres.x;
    float r1 = fmaxf(dy * inv * g2.y + be2.y, 0.0f) + hres.y;
    hp[lane] = make_float2(r0, r1);

    if (last) {
        float2 w2 = ((const float2*)Wout)[lane];
        float o_ = r0 * w2.x + r1 * w2.y;
#pragma unroll
        for (int o = 16; o; o >>= 1) o_ += __shfl_xor_sync(0xFFFFFFFFu, o_, o);
        if (lane == 0) out[node] = o_ + bout[0];
    }
}

// ---------------- launch ----------------

extern "C" void kernel_launch(void* const* d_in, const int* in_sizes, int n_in,
                              void* d_out, int out_size) {
    const float* x      = (const float*)d_in[0];
    const int*   ei     = (const int*)d_in[1];
    const float* W_in   = (const float*)d_in[2];
    const float* b_in   = (const float*)d_in[3];
    const float* W_conv = (const float*)d_in[4];
    const float* b_conv = (const float*)d_in[5];
    const float* gamma  = (const float*)d_in[6];
    const float* beta   = (const float*)d_in[7];
    const float* W_out  = (const float*)d_in[8];
    const float* b_out  = (const float*)d_in[9];
    float* out = (float*)d_out;

    int N = in_sizes[0] / IN_DIM;
    int E = in_sizes[1] / 2;
    int nblk_scan = (N + 1023) / 1024;

    // CSR build + dinv
    zero_cnt<<<(N + 255) / 256, 256>>>(N);
    count_kernel<<<(E + 255) / 256, 256>>>(ei + E, E);
    scanA<<<nblk_scan, 1024>>>(N);
    scanB<<<1, 32>>>(nblk_scan);
    scanC<<<(N + 255) / 256, 256>>>(N, E);
    build_kernel<<<(E + 255) / 256, 256>>>(ei, E);

    in_gemm<<<(N + 31) / 32, 256>>>(x, W_in, b_in, N);

    for (int l = 0; l < 3; l++) {
        conv_gemm<<<(N + 63) / 64, 256>>>(W_conv + l * H * H, N);
        gather_ln<<<(N + 7) / 8, 256>>>(b_conv + l * H, gamma + l * H, beta + l * H,
                                        W_out, b_out, out, N, l == 2);
    }
}